// round 6
// baseline (speedup 1.0000x reference)
#include <cuda_runtime.h>
#include <math.h>
#include <stdint.h>

typedef unsigned long long u64;

#define GMAX 10240
#define PMAX (GMAX / 2)
#define NW 8
#define BLOCK 256
#define RPB 64
#define CHP 192   // g-pairs per smem chunk (2*192*96 = 36KB < 48KB static cap)

// g-pair packed tables (no duplication):
// T1 (pass 1): v[0..8] = {Yi[g0], Yi[g1]} pairs, v[9] = pad      -> 80 B
// T2 (pass 2): v[0..8] = Y pairs, v[9]=gx pair, v[10]=gy, v[11]=gz -> 96 B
struct __align__(16) T1e { u64 v[10]; };
struct __align__(16) T2e { u64 v[12]; };
__device__ T1e g_T1[PMAX];
__device__ T2e g_T2[PMAX];

__device__ __forceinline__ u64 dup2(float f) {
    u64 r; asm("mov.b64 %0, {%1, %1};" : "=l"(r) : "f"(f)); return r;
}
__device__ __forceinline__ u64 pk2(float lo, float hi) {
    u64 r; asm("mov.b64 %0, {%1, %2};" : "=l"(r) : "f"(lo), "f"(hi)); return r;
}
__device__ __forceinline__ void upk2(u64 v, float& lo, float& hi) {
    asm("mov.b64 {%0, %1}, %2;" : "=f"(lo), "=f"(hi) : "l"(v));
}
__device__ __forceinline__ u64 fma2(u64 a, u64 b, u64 c) {
    u64 r; asm("fma.rn.f32x2 %0, %1, %2, %3;" : "=l"(r) : "l"(a), "l"(b), "l"(c)); return r;
}
__device__ __forceinline__ u64 mul2(u64 a, u64 b) {
    u64 r; asm("mul.rn.f32x2 %0, %1, %2;" : "=l"(r) : "l"(a), "l"(b)); return r;
}

// 9-term SH dot, SINGLE sequential chain per f32x2 half — exact R1 rounding
// order (verified rel_err 4.8e-8). DO NOT re-associate.
__device__ __forceinline__ u64 sig9p(const u64* C, ulonglong2 q0, ulonglong2 q1,
                                     ulonglong2 q2, ulonglong2 q3, u64 y8) {
    u64 acc = mul2(C[0], q0.x);
    acc = fma2(C[1], q0.y, acc);
    acc = fma2(C[2], q1.x, acc);
    acc = fma2(C[3], q1.y, acc);
    acc = fma2(C[4], q2.x, acc);
    acc = fma2(C[5], q2.y, acc);
    acc = fma2(C[6], q3.x, acc);
    acc = fma2(C[7], q3.y, acc);
    acc = fma2(C[8], y8, acc);
    return acc;
}
__device__ __forceinline__ u64 dot3p(u64 zx, u64 zy, u64 zz, u64 gx, u64 gy, u64 gz) {
    u64 d = mul2(zx, gx);
    d = fma2(zy, gy, d);
    return fma2(zz, gz, d);
}
// lower-g half checked first -> first-index tie-break preserved (strict >)
__device__ __forceinline__ void amax2(u64 s, int g0, float& bv, int& bi) {
    float lo, hi; upk2(s, lo, hi);
    if (lo > bv) { bv = lo; bi = g0; }
    if (hi > bv) { bv = hi; bi = g0 + 1; }
}
__device__ __forceinline__ void amaxm2(u64 s, u64 d, int g0, float& bv, int& bi) {
    float lo, hi, dl, dh; upk2(s, lo, hi); upk2(d, dl, dh);
    if (fabsf(dl) < 0.2f && lo > bv) { bv = lo; bi = g0; }
    if (fabsf(dh) < 0.2f && hi > bv) { bv = hi; bi = g0 + 1; }
}

__device__ __forceinline__ void shY(const float* __restrict__ grid, int g,
                                    float* Y, float* gv) {
    float gx = grid[3 * g + 0], gy = grid[3 * g + 1], gz = grid[3 * g + 2];
    gv[0] = gx; gv[1] = gy; gv[2] = gz;
    float n = sqrtf(gx * gx + gy * gy + gz * gz);
    float inv = 1.0f / fmaxf(n, 1e-12f);
    float x = gx * inv, y = gy * inv, z = gz * inv;
    float x2 = x * x, y2 = y * y, z2 = z * z;
    Y[0] = 2.5033429417967046f * (x * y * (x2 - y2));
    Y[1] = 1.7701307697799304f * (y * z * (3.0f * x2 - y2));
    Y[2] = 0.9461746957575601f * (x * y * (7.0f * z2 - 1.0f));
    Y[3] = 0.6690465435572892f * (y * z * (7.0f * z2 - 3.0f));
    Y[4] = 0.10578554691520431f * (35.0f * z2 * z2 - 30.0f * z2 + 3.0f);
    Y[5] = 0.6690465435572892f * (x * z * (7.0f * z2 - 3.0f));
    Y[6] = 0.47308734787878004f * ((x2 - y2) * (7.0f * z2 - 1.0f));
    Y[7] = 1.7701307697799304f * (x * z * (x2 - y2));
    Y[8] = 0.6258357354491761f * (x2 * x2 - 6.0f * x2 * y2 + y2 * y2);
}

__global__ void sh_precompute(const float* __restrict__ grid, int G, int P) {
    int p = blockIdx.x * blockDim.x + threadIdx.x;
    if (p >= P) return;
    int g0 = 2 * p;
    int g1 = min(2 * p + 1, G - 1);   // odd-G pad = copy of last (tie-break safe)
    float Ya[9], Yb[9], ga[3], gb[3];
    shY(grid, g0, Ya, ga);
    shY(grid, g1, Yb, gb);
    T1e t1; T2e t2;
#pragma unroll
    for (int i = 0; i < 9; i++) {
        u64 pr = pk2(Ya[i], Yb[i]);
        t1.v[i] = pr; t2.v[i] = pr;
    }
    t1.v[9] = 0;
    t2.v[9]  = pk2(ga[0], gb[0]);
    t2.v[10] = pk2(ga[1], gb[1]);
    t2.v[11] = pk2(ga[2], gb[2]);
    g_T1[p] = t1;
    g_T2[p] = t2;
}

__device__ __forceinline__ void stage16(const char* gsrc, uint32_t sdst, int bytes, int tid) {
    for (int i = tid * 16; i < bytes; i += BLOCK * 16)
        asm volatile("cp.async.cg.shared.global [%0], [%1], 16;"
                     :: "r"(sdst + (uint32_t)i), "l"(gsrc + i));
}
#define CPA_COMMIT() asm volatile("cp.async.commit_group;" ::: "memory")
#define CPA_WAIT1()  asm volatile("cp.async.wait_group 1;" ::: "memory")

// ---------------------------------------------------------------------------
// 256 threads = 8 warps; 64 rows/block (2 rows per lane); f32x2 packs (g,g+1).
// Warps split the pair range of each staged chunk. Double-buffered cp.async.
// 3 blocks/SM (reg cap 84) for latency hiding.
// ---------------------------------------------------------------------------
__global__ __launch_bounds__(BLOCK, 3) void decoder_kernel(
    const float* __restrict__ f0,
    const float* __restrict__ f4,
    const float* __restrict__ grid,
    float* __restrict__ out,
    int B, int G)
{
    __shared__ __align__(16) char sbuf[2][CHP * 96];
    __shared__ float s_pv[NW][RPB];
    __shared__ int s_pidx[NW][RPB];
    __shared__ float s_z[RPB][3];

    const int tid = threadIdx.x;
    const int lane = tid & 31;
    const int wid = tid >> 5;
    const int rowbase = blockIdx.x * RPB;
    const float NEG_INF = __int_as_float(0xff800000);

    const int rA = rowbase + lane;        // row for chain A
    const int rB = rA + 32;               // row for chain B

    u64 FA[9], FB[9];
#pragma unroll
    for (int i = 0; i < 9; i++) {
        FA[i] = dup2((rA < B) ? f4[rA * 9 + i] : 0.0f);
        FB[i] = dup2((rB < B) ? f4[rB * 9 + i] : 0.0f);
    }

    const int P = (G + 1) / 2;
    const int nch = (P + CHP - 1) / CHP;
    uint32_t sb[2];
    sb[0] = (uint32_t)__cvta_generic_to_shared(sbuf[0]);
    sb[1] = (uint32_t)__cvta_generic_to_shared(sbuf[1]);

    float bvA = NEG_INF, bvB = NEG_INF;
    int biA = 0, biB = 0;

    // ----------------------------- pass 1 ----------------------------------
    stage16((const char*)g_T1, sb[0], min(CHP, P) * 80, tid);
    CPA_COMMIT();
    for (int c = 0; c < nch; c++) {
        int nxt = c + 1;
        if (nxt < nch)
            stage16((const char*)(g_T1 + nxt * CHP), sb[nxt & 1],
                    min(CHP, P - nxt * CHP) * 80, tid);
        CPA_COMMIT();
        CPA_WAIT1();
        __syncthreads();
        const char* buf = sbuf[c & 1];
        const int cnt = min(CHP, P - c * CHP);
        const int gb = c * CHP * 2;
        for (int k = wid; k < cnt; k += NW) {
            const ulonglong2* e = (const ulonglong2*)(buf + k * 80);
            ulonglong2 q0 = e[0], q1 = e[1], q2 = e[2], q3 = e[3], q4 = e[4];
            u64 aA = sig9p(FA, q0, q1, q2, q3, q4.x);
            u64 aB = sig9p(FB, q0, q1, q2, q3, q4.x);
            int g0 = gb + 2 * k;
            amax2(aA, g0, bvA, biA);
            amax2(aB, g0, bvB, biB);
        }
        __syncthreads();
    }

    s_pv[wid][lane] = bvA;      s_pidx[wid][lane] = biA;
    s_pv[wid][lane + 32] = bvB; s_pidx[wid][lane + 32] = biB;
    __syncthreads();
    if (tid < RPB) {
        float v = s_pv[0][tid]; int idx = s_pidx[0][tid];
#pragma unroll
        for (int w = 1; w < NW; w++) {
            float ov = s_pv[w][tid]; int oi = s_pidx[w][tid];
            if (ov > v || (ov == v && oi < idx)) { v = ov; idx = oi; }
        }
        s_z[tid][0] = grid[3 * idx + 0];
        s_z[tid][1] = grid[3 * idx + 1];
        s_z[tid][2] = grid[3 * idx + 2];
    }
    __syncthreads();

    const u64 ZAx = dup2(s_z[lane][0]),      ZAy = dup2(s_z[lane][1]),      ZAz = dup2(s_z[lane][2]);
    const u64 ZBx = dup2(s_z[lane + 32][0]), ZBy = dup2(s_z[lane + 32][1]), ZBz = dup2(s_z[lane + 32][2]);

    bvA = NEG_INF; bvB = NEG_INF; biA = 0; biB = 0;

    // ----------------------------- pass 2 ----------------------------------
    stage16((const char*)g_T2, sb[0], min(CHP, P) * 96, tid);
    CPA_COMMIT();
    for (int c = 0; c < nch; c++) {
        int nxt = c + 1;
        if (nxt < nch)
            stage16((const char*)(g_T2 + nxt * CHP), sb[nxt & 1],
                    min(CHP, P - nxt * CHP) * 96, tid);
        CPA_COMMIT();
        CPA_WAIT1();
        __syncthreads();
        const char* buf = sbuf[c & 1];
        const int cnt = min(CHP, P - c * CHP);
        const int gb = c * CHP * 2;
        for (int k = wid; k < cnt; k += NW) {
            const ulonglong2* e = (const ulonglong2*)(buf + k * 96);
            ulonglong2 q0 = e[0], q1 = e[1], q2 = e[2], q3 = e[3], q4 = e[4], q5 = e[5];
            u64 aA = sig9p(FA, q0, q1, q2, q3, q4.x);
            u64 aB = sig9p(FB, q0, q1, q2, q3, q4.x);
            u64 dA = dot3p(ZAx, ZAy, ZAz, q4.y, q5.x, q5.y);
            u64 dB = dot3p(ZBx, ZBy, ZBz, q4.y, q5.x, q5.y);
            int g0 = gb + 2 * k;
            amaxm2(aA, dA, g0, bvA, biA);
            amaxm2(aB, dB, g0, bvB, biB);
        }
        __syncthreads();
    }

    s_pv[wid][lane] = bvA;      s_pidx[wid][lane] = biA;
    s_pv[wid][lane + 32] = bvB; s_pidx[wid][lane + 32] = biB;
    __syncthreads();

    // ----------------------------- epilogue --------------------------------
    if (tid < RPB) {
        int row = rowbase + tid;
        if (row < B) {
            float v = s_pv[0][tid]; int idx = s_pidx[0][tid];
#pragma unroll
            for (int w = 1; w < NW; w++) {
                float ov = s_pv[w][tid]; int oi = s_pidx[w][tid];
                if (ov > v || (ov == v && oi < idx)) { v = ov; idx = oi; }
            }
            float xr0 = grid[3 * idx + 0], xr1 = grid[3 * idx + 1], xr2 = grid[3 * idx + 2];
            float zr0 = s_z[tid][0], zr1 = s_z[tid][1], zr2 = s_z[tid][2];
            float zn = sqrtf(zr0 * zr0 + zr1 * zr1 + zr2 * zr2);
            float zinv = 1.0f / fmaxf(zn, 1e-12f);
            float z0 = zr0 * zinv, z1 = zr1 * zinv, z2 = zr2 * zinv;
            float pr = xr0 * z0 + xr1 * z1 + xr2 * z2;
            float x0 = xr0 - pr * z0, x1 = xr1 - pr * z1, x2 = xr2 - pr * z2;
            float xn = sqrtf(x0 * x0 + x1 * x1 + x2 * x2);
            float xinv = 1.0f / fmaxf(xn, 1e-12f);
            x0 *= xinv; x1 *= xinv; x2 *= xinv;
            float y0 = z1 * x2 - z2 * x1;
            float y1 = z2 * x0 - z0 * x2;
            float y2 = z0 * x1 - z1 * x0;
            float m00 = x0, m01 = y0, m02 = z0;
            float m10 = x1, m11 = y1, m12 = z1;
            float m20 = x2, m21 = y2, m22 = z2;
            float qa0 = sqrtf(fmaxf(1.0f + m00 + m11 + m22, 0.0f));
            float qa1 = sqrtf(fmaxf(1.0f + m00 - m11 - m22, 0.0f));
            float qa2 = sqrtf(fmaxf(1.0f - m00 + m11 - m22, 0.0f));
            float qa3 = sqrtf(fmaxf(1.0f - m00 - m11 + m22, 0.0f));
            float c0[4] = {qa0 * qa0, m21 - m12, m02 - m20, m10 - m01};
            float c1[4] = {m21 - m12, qa1 * qa1, m10 + m01, m02 + m20};
            float c2[4] = {m02 - m20, m10 + m01, qa2 * qa2, m12 + m21};
            float c3[4] = {m10 - m01, m20 + m02, m21 + m12, qa3 * qa3};
            int best = 0; float bq = qa0;
            if (qa1 > bq) { bq = qa1; best = 1; }
            if (qa2 > bq) { bq = qa2; best = 2; }
            if (qa3 > bq) { bq = qa3; best = 3; }
            const float* cr = (best == 0) ? c0 : (best == 1) ? c1 : (best == 2) ? c2 : c3;
            float dn = 2.0f * fmaxf(bq, 0.1f);
            out[row * 4 + 0] = cr[0] / dn;
            out[row * 4 + 1] = cr[1] / dn;
            out[row * 4 + 2] = cr[2] / dn;
            out[row * 4 + 3] = cr[3] / dn;
            out[4 * B + row] = f0[row] * 57.29577951308232f;
        }
    }
}

extern "C" void kernel_launch(void* const* d_in, const int* in_sizes, int n_in,
                              void* d_out, int out_size) {
    const float* f0 = (const float*)d_in[0];
    const float* f4 = (const float*)d_in[2];
    const float* grid = (const float*)d_in[4];
    int B = in_sizes[0];          // f0: [B,1]
    int G = in_sizes[4] / 3;      // grid_vecs: [G,3]
    if (G > GMAX) G = GMAX;
    int P = (G + 1) / 2;

    sh_precompute<<<(P + 255) / 256, 256>>>(grid, G, P);

    int blocks = (B + RPB - 1) / RPB;
    decoder_kernel<<<blocks, BLOCK>>>(f0, f4, grid, (float*)d_out, B, G);
}

// round 7
// speedup vs baseline: 1.0765x; 1.0765x over previous
#include <cuda_runtime.h>
#include <math.h>
#include <stdint.h>

typedef unsigned long long u64;

#define GMAX 10240
#define PMAX (GMAX / 2)
#define BMAX 32768
#define NW 8
#define BLOCK 256
#define RPB 64
#define CHP 192
#define SPLIT 4

// g-pair packed tables (no duplication):
// T1 (pass 1): v[0..8] = {Yi[g0], Yi[g1]} pairs, v[9] = pad      -> 80 B
// T2 (pass 2): v[0..8] = Y pairs, v[9]=gx pair, v[10]=gy, v[11]=gz -> 96 B
struct __align__(16) T1e { u64 v[10]; };
struct __align__(16) T2e { u64 v[12]; };
__device__ T1e g_T1[PMAX];
__device__ T2e g_T2[PMAX];

// cross-block reduction scratch: packed (sortable_value<<32 | ~index)
__device__ u64 g_part1[BMAX];
__device__ u64 g_part2[BMAX];
__device__ float4 g_zax[BMAX];

// packed(-inf, idx=0): key(-inf)=0x007FFFFF, ~0 = 0xFFFFFFFF
#define INIT_CAND 0x007FFFFFFFFFFFFFULL

__device__ __forceinline__ u64 packcand(float v, int idx) {
    unsigned b = __float_as_uint(v);
    unsigned key = (b & 0x80000000u) ? ~b : (b | 0x80000000u);
    return ((u64)key << 32) | (unsigned)(~idx);
}

__device__ __forceinline__ u64 dup2(float f) {
    u64 r; asm("mov.b64 %0, {%1, %1};" : "=l"(r) : "f"(f)); return r;
}
__device__ __forceinline__ u64 pk2(float lo, float hi) {
    u64 r; asm("mov.b64 %0, {%1, %2};" : "=l"(r) : "f"(lo), "f"(hi)); return r;
}
__device__ __forceinline__ void upk2(u64 v, float& lo, float& hi) {
    asm("mov.b64 {%0, %1}, %2;" : "=f"(lo), "=f"(hi) : "l"(v));
}
__device__ __forceinline__ u64 fma2(u64 a, u64 b, u64 c) {
    u64 r; asm("fma.rn.f32x2 %0, %1, %2, %3;" : "=l"(r) : "l"(a), "l"(b), "l"(c)); return r;
}
__device__ __forceinline__ u64 mul2(u64 a, u64 b) {
    u64 r; asm("mul.rn.f32x2 %0, %1, %2;" : "=l"(r) : "l"(a), "l"(b)); return r;
}

// 9-term SH dot, SINGLE sequential chain per f32x2 half — exact R1 rounding
// order (verified rel_err 4.8e-8). DO NOT re-associate.
__device__ __forceinline__ u64 sig9p(const u64* C, ulonglong2 q0, ulonglong2 q1,
                                     ulonglong2 q2, ulonglong2 q3, u64 y8) {
    u64 acc = mul2(C[0], q0.x);
    acc = fma2(C[1], q0.y, acc);
    acc = fma2(C[2], q1.x, acc);
    acc = fma2(C[3], q1.y, acc);
    acc = fma2(C[4], q2.x, acc);
    acc = fma2(C[5], q2.y, acc);
    acc = fma2(C[6], q3.x, acc);
    acc = fma2(C[7], q3.y, acc);
    acc = fma2(C[8], y8, acc);
    return acc;
}
__device__ __forceinline__ u64 dot3p(u64 zx, u64 zy, u64 zz, u64 gx, u64 gy, u64 gz) {
    u64 d = mul2(zx, gx);
    d = fma2(zy, gy, d);
    return fma2(zz, gz, d);
}
__device__ __forceinline__ void amax2(u64 s, int g0, float& bv, int& bi) {
    float lo, hi; upk2(s, lo, hi);
    if (lo > bv) { bv = lo; bi = g0; }
    if (hi > bv) { bv = hi; bi = g0 + 1; }
}
__device__ __forceinline__ void amaxm2(u64 s, u64 d, int g0, float& bv, int& bi) {
    float lo, hi, dl, dh; upk2(s, lo, hi); upk2(d, dl, dh);
    if (fabsf(dl) < 0.2f && lo > bv) { bv = lo; bi = g0; }
    if (fabsf(dh) < 0.2f && hi > bv) { bv = hi; bi = g0 + 1; }
}

__device__ __forceinline__ void shY(const float* __restrict__ grid, int g,
                                    float* Y, float* gv) {
    float gx = grid[3 * g + 0], gy = grid[3 * g + 1], gz = grid[3 * g + 2];
    gv[0] = gx; gv[1] = gy; gv[2] = gz;
    float n = sqrtf(gx * gx + gy * gy + gz * gz);
    float inv = 1.0f / fmaxf(n, 1e-12f);
    float x = gx * inv, y = gy * inv, z = gz * inv;
    float x2 = x * x, y2 = y * y, z2 = z * z;
    Y[0] = 2.5033429417967046f * (x * y * (x2 - y2));
    Y[1] = 1.7701307697799304f * (y * z * (3.0f * x2 - y2));
    Y[2] = 0.9461746957575601f * (x * y * (7.0f * z2 - 1.0f));
    Y[3] = 0.6690465435572892f * (y * z * (7.0f * z2 - 3.0f));
    Y[4] = 0.10578554691520431f * (35.0f * z2 * z2 - 30.0f * z2 + 3.0f);
    Y[5] = 0.6690465435572892f * (x * z * (7.0f * z2 - 3.0f));
    Y[6] = 0.47308734787878004f * ((x2 - y2) * (7.0f * z2 - 1.0f));
    Y[7] = 1.7701307697799304f * (x * z * (x2 - y2));
    Y[8] = 0.6258357354491761f * (x2 * x2 - 6.0f * x2 * y2 + y2 * y2);
}

__global__ void sh_precompute(const float* __restrict__ grid, int G, int P) {
    int p = blockIdx.x * blockDim.x + threadIdx.x;
    if (p >= P) return;
    int g0 = 2 * p;
    int g1 = min(2 * p + 1, G - 1);
    float Ya[9], Yb[9], ga[3], gb[3];
    shY(grid, g0, Ya, ga);
    shY(grid, g1, Yb, gb);
    T1e t1; T2e t2;
#pragma unroll
    for (int i = 0; i < 9; i++) {
        u64 pr = pk2(Ya[i], Yb[i]);
        t1.v[i] = pr; t2.v[i] = pr;
    }
    t1.v[9] = 0;
    t2.v[9]  = pk2(ga[0], gb[0]);
    t2.v[10] = pk2(ga[1], gb[1]);
    t2.v[11] = pk2(ga[2], gb[2]);
    g_T1[p] = t1;
    g_T2[p] = t2;
}

__global__ void init_parts(int B) {
    int i = blockIdx.x * blockDim.x + threadIdx.x;
    if (i < B) { g_part1[i] = INIT_CAND; g_part2[i] = INIT_CAND; }
}

__device__ __forceinline__ void stage16(const char* gsrc, uint32_t sdst, int bytes, int tid) {
    for (int i = tid * 16; i < bytes; i += BLOCK * 16)
        asm volatile("cp.async.cg.shared.global [%0], [%1], 16;"
                     :: "r"(sdst + (uint32_t)i), "l"(gsrc + i));
}
#define CPA_COMMIT() asm volatile("cp.async.commit_group;" ::: "memory")
#define CPA_WAIT1()  asm volatile("cp.async.wait_group 1;" ::: "memory")

// ---------------------------------------------------------------------------
// Pass 1: blockIdx.x selects 64 rows, blockIdx.y selects g-range quarter.
// Partial per-row argmax merged globally via atomicMax on packed u64 keys.
// ---------------------------------------------------------------------------
__global__ __launch_bounds__(BLOCK, 3) void pass1_kernel(
    const float* __restrict__ f4, int B, int P, int Pq)
{
    __shared__ __align__(16) char sbuf[2][CHP * 80];
    __shared__ float s_pv[NW][RPB];
    __shared__ int s_pidx[NW][RPB];

    const int tid = threadIdx.x;
    const int lane = tid & 31;
    const int wid = tid >> 5;
    const int rowbase = blockIdx.x * RPB;
    const int p0 = blockIdx.y * Pq;
    const int np = min(P - p0, Pq);
    const float NEG_INF = __int_as_float(0xff800000);

    const int rA = rowbase + lane;
    const int rB = rA + 32;

    u64 FA[9], FB[9];
#pragma unroll
    for (int i = 0; i < 9; i++) {
        FA[i] = dup2((rA < B) ? f4[rA * 9 + i] : 0.0f);
        FB[i] = dup2((rB < B) ? f4[rB * 9 + i] : 0.0f);
    }

    const int nch = (np + CHP - 1) / CHP;
    uint32_t sb[2];
    sb[0] = (uint32_t)__cvta_generic_to_shared(sbuf[0]);
    sb[1] = (uint32_t)__cvta_generic_to_shared(sbuf[1]);

    float bvA = NEG_INF, bvB = NEG_INF;
    int biA = 0, biB = 0;

    stage16((const char*)(g_T1 + p0), sb[0], min(CHP, np) * 80, tid);
    CPA_COMMIT();
    for (int c = 0; c < nch; c++) {
        int nxt = c + 1;
        if (nxt < nch)
            stage16((const char*)(g_T1 + p0 + nxt * CHP), sb[nxt & 1],
                    min(CHP, np - nxt * CHP) * 80, tid);
        CPA_COMMIT();
        CPA_WAIT1();
        __syncthreads();
        const char* buf = sbuf[c & 1];
        const int cnt = min(CHP, np - c * CHP);
        const int gb = (p0 + c * CHP) * 2;
        for (int k = wid; k < cnt; k += NW) {
            const ulonglong2* e = (const ulonglong2*)(buf + k * 80);
            ulonglong2 q0 = e[0], q1 = e[1], q2 = e[2], q3 = e[3], q4 = e[4];
            u64 aA = sig9p(FA, q0, q1, q2, q3, q4.x);
            u64 aB = sig9p(FB, q0, q1, q2, q3, q4.x);
            int g0 = gb + 2 * k;
            amax2(aA, g0, bvA, biA);
            amax2(aB, g0, bvB, biB);
        }
        __syncthreads();
    }

    s_pv[wid][lane] = bvA;      s_pidx[wid][lane] = biA;
    s_pv[wid][lane + 32] = bvB; s_pidx[wid][lane + 32] = biB;
    __syncthreads();
    if (tid < RPB) {
        int row = rowbase + tid;
        if (row < B) {
            float v = s_pv[0][tid]; int idx = s_pidx[0][tid];
#pragma unroll
            for (int w = 1; w < NW; w++) {
                float ov = s_pv[w][tid]; int oi = s_pidx[w][tid];
                if (ov > v || (ov == v && oi < idx)) { v = ov; idx = oi; }
            }
            atomicMax((unsigned long long*)&g_part1[row], packcand(v, idx));
        }
    }
}

__global__ void select_z(const float* __restrict__ grid, int B) {
    int i = blockIdx.x * blockDim.x + threadIdx.x;
    if (i >= B) return;
    int idx = ~(unsigned)g_part1[i];
    g_zax[i] = make_float4(grid[3 * idx + 0], grid[3 * idx + 1], grid[3 * idx + 2], 0.0f);
}

// ---------------------------------------------------------------------------
// Pass 2: masked argmax, same split structure, z axes from g_zax.
// ---------------------------------------------------------------------------
__global__ __launch_bounds__(BLOCK, 3) void pass2_kernel(
    const float* __restrict__ f4, int B, int P, int Pq)
{
    __shared__ __align__(16) char sbuf[2][CHP * 96];
    __shared__ float s_pv[NW][RPB];
    __shared__ int s_pidx[NW][RPB];

    const int tid = threadIdx.x;
    const int lane = tid & 31;
    const int wid = tid >> 5;
    const int rowbase = blockIdx.x * RPB;
    const int p0 = blockIdx.y * Pq;
    const int np = min(P - p0, Pq);
    const float NEG_INF = __int_as_float(0xff800000);

    const int rA = rowbase + lane;
    const int rB = rA + 32;

    u64 FA[9], FB[9];
#pragma unroll
    for (int i = 0; i < 9; i++) {
        FA[i] = dup2((rA < B) ? f4[rA * 9 + i] : 0.0f);
        FB[i] = dup2((rB < B) ? f4[rB * 9 + i] : 0.0f);
    }
    float4 zA = (rA < B) ? g_zax[rA] : make_float4(0, 0, 0, 0);
    float4 zB = (rB < B) ? g_zax[rB] : make_float4(0, 0, 0, 0);
    const u64 ZAx = dup2(zA.x), ZAy = dup2(zA.y), ZAz = dup2(zA.z);
    const u64 ZBx = dup2(zB.x), ZBy = dup2(zB.y), ZBz = dup2(zB.z);

    const int nch = (np + CHP - 1) / CHP;
    uint32_t sb[2];
    sb[0] = (uint32_t)__cvta_generic_to_shared(sbuf[0]);
    sb[1] = (uint32_t)__cvta_generic_to_shared(sbuf[1]);

    float bvA = NEG_INF, bvB = NEG_INF;
    int biA = 0, biB = 0;

    stage16((const char*)(g_T2 + p0), sb[0], min(CHP, np) * 96, tid);
    CPA_COMMIT();
    for (int c = 0; c < nch; c++) {
        int nxt = c + 1;
        if (nxt < nch)
            stage16((const char*)(g_T2 + p0 + nxt * CHP), sb[nxt & 1],
                    min(CHP, np - nxt * CHP) * 96, tid);
        CPA_COMMIT();
        CPA_WAIT1();
        __syncthreads();
        const char* buf = sbuf[c & 1];
        const int cnt = min(CHP, np - c * CHP);
        const int gb = (p0 + c * CHP) * 2;
        for (int k = wid; k < cnt; k += NW) {
            const ulonglong2* e = (const ulonglong2*)(buf + k * 96);
            ulonglong2 q0 = e[0], q1 = e[1], q2 = e[2], q3 = e[3], q4 = e[4], q5 = e[5];
            u64 aA = sig9p(FA, q0, q1, q2, q3, q4.x);
            u64 aB = sig9p(FB, q0, q1, q2, q3, q4.x);
            u64 dA = dot3p(ZAx, ZAy, ZAz, q4.y, q5.x, q5.y);
            u64 dB = dot3p(ZBx, ZBy, ZBz, q4.y, q5.x, q5.y);
            int g0 = gb + 2 * k;
            amaxm2(aA, dA, g0, bvA, biA);
            amaxm2(aB, dB, g0, bvB, biB);
        }
        __syncthreads();
    }

    s_pv[wid][lane] = bvA;      s_pidx[wid][lane] = biA;
    s_pv[wid][lane + 32] = bvB; s_pidx[wid][lane + 32] = biB;
    __syncthreads();
    if (tid < RPB) {
        int row = rowbase + tid;
        if (row < B) {
            float v = s_pv[0][tid]; int idx = s_pidx[0][tid];
#pragma unroll
            for (int w = 1; w < NW; w++) {
                float ov = s_pv[w][tid]; int oi = s_pidx[w][tid];
                if (ov > v || (ov == v && oi < idx)) { v = ov; idx = oi; }
            }
            atomicMax((unsigned long long*)&g_part2[row], packcand(v, idx));
        }
    }
}

// ---------------------------------------------------------------------------
// Epilogue: Gram-Schmidt + matrix->quaternion + boundary map.
// ---------------------------------------------------------------------------
__global__ void epilogue_kernel(const float* __restrict__ f0,
                                const float* __restrict__ grid,
                                float* __restrict__ out, int B)
{
    int row = blockIdx.x * blockDim.x + threadIdx.x;
    if (row >= B) return;
    int idx = ~(unsigned)g_part2[row];
    float xr0 = grid[3 * idx + 0], xr1 = grid[3 * idx + 1], xr2 = grid[3 * idx + 2];
    float4 zr = g_zax[row];
    float zn = sqrtf(zr.x * zr.x + zr.y * zr.y + zr.z * zr.z);
    float zinv = 1.0f / fmaxf(zn, 1e-12f);
    float z0 = zr.x * zinv, z1 = zr.y * zinv, z2 = zr.z * zinv;
    float pr = xr0 * z0 + xr1 * z1 + xr2 * z2;
    float x0 = xr0 - pr * z0, x1 = xr1 - pr * z1, x2 = xr2 - pr * z2;
    float xn = sqrtf(x0 * x0 + x1 * x1 + x2 * x2);
    float xinv = 1.0f / fmaxf(xn, 1e-12f);
    x0 *= xinv; x1 *= xinv; x2 *= xinv;
    float y0 = z1 * x2 - z2 * x1;
    float y1 = z2 * x0 - z0 * x2;
    float y2 = z0 * x1 - z1 * x0;
    float m00 = x0, m01 = y0, m02 = z0;
    float m10 = x1, m11 = y1, m12 = z1;
    float m20 = x2, m21 = y2, m22 = z2;
    float qa0 = sqrtf(fmaxf(1.0f + m00 + m11 + m22, 0.0f));
    float qa1 = sqrtf(fmaxf(1.0f + m00 - m11 - m22, 0.0f));
    float qa2 = sqrtf(fmaxf(1.0f - m00 + m11 - m22, 0.0f));
    float qa3 = sqrtf(fmaxf(1.0f - m00 - m11 + m22, 0.0f));
    float c0[4] = {qa0 * qa0, m21 - m12, m02 - m20, m10 - m01};
    float c1[4] = {m21 - m12, qa1 * qa1, m10 + m01, m02 + m20};
    float c2[4] = {m02 - m20, m10 + m01, qa2 * qa2, m12 + m21};
    float c3[4] = {m10 - m01, m20 + m02, m21 + m12, qa3 * qa3};
    int best = 0; float bq = qa0;
    if (qa1 > bq) { bq = qa1; best = 1; }
    if (qa2 > bq) { bq = qa2; best = 2; }
    if (qa3 > bq) { bq = qa3; best = 3; }
    const float* cr = (best == 0) ? c0 : (best == 1) ? c1 : (best == 2) ? c2 : c3;
    float dn = 2.0f * fmaxf(bq, 0.1f);
    out[row * 4 + 0] = cr[0] / dn;
    out[row * 4 + 1] = cr[1] / dn;
    out[row * 4 + 2] = cr[2] / dn;
    out[row * 4 + 3] = cr[3] / dn;
    out[4 * B + row] = f0[row] * 57.29577951308232f;
}

extern "C" void kernel_launch(void* const* d_in, const int* in_sizes, int n_in,
                              void* d_out, int out_size) {
    const float* f0 = (const float*)d_in[0];
    const float* f4 = (const float*)d_in[2];
    const float* grid = (const float*)d_in[4];
    int B = in_sizes[0];
    int G = in_sizes[4] / 3;
    if (G > GMAX) G = GMAX;
    if (B > BMAX) B = BMAX;
    int P = (G + 1) / 2;
    int Pq = (P + SPLIT - 1) / SPLIT;

    sh_precompute<<<(P + 255) / 256, 256>>>(grid, G, P);
    init_parts<<<(B + 255) / 256, 256>>>(B);

    dim3 g1((B + RPB - 1) / RPB, SPLIT);
    pass1_kernel<<<g1, BLOCK>>>(f4, B, P, Pq);
    select_z<<<(B + 255) / 256, 256>>>(grid, B);
    pass2_kernel<<<g1, BLOCK>>>(f4, B, P, Pq);
    epilogue_kernel<<<(B + 255) / 256, 256>>>(f0, grid, (float*)d_out, B);
}

// round 8
// speedup vs baseline: 1.1259x; 1.0459x over previous
#include <cuda_runtime.h>
#include <math.h>
#include <stdint.h>

typedef unsigned long long u64;

#define GMAX 10240
#define PMAX (GMAX / 2)
#define BMAX 32768
#define NW 8
#define BLOCK 256
#define RPB 64
#define CHP 192
#define SPLIT 5

// g-pair packed tables (no duplication):
// T1 (pass 1): v[0..8] = {Yi[g0], Yi[g1]} pairs, v[9] = pad      -> 80 B
// T2 (pass 2): v[0..8] = Y pairs, v[9]=gx pair, v[10]=gy, v[11]=gz -> 96 B
struct __align__(16) T1e { u64 v[10]; };
struct __align__(16) T2e { u64 v[12]; };
__device__ T1e g_T1[PMAX];
__device__ T2e g_T2[PMAX];

// cross-block reduction scratch: packed (sortable_value<<32 | ~index)
__device__ u64 g_part1[BMAX];
__device__ u64 g_part2[BMAX];

// packed(-inf, idx=0): key(-inf)=0x007FFFFF, ~0 = 0xFFFFFFFF
#define INIT_CAND 0x007FFFFFFFFFFFFFULL

__device__ __forceinline__ u64 packcand(float v, int idx) {
    unsigned b = __float_as_uint(v);
    unsigned key = (b & 0x80000000u) ? ~b : (b | 0x80000000u);
    return ((u64)key << 32) | (unsigned)(~idx);
}

__device__ __forceinline__ u64 dup2(float f) {
    u64 r; asm("mov.b64 %0, {%1, %1};" : "=l"(r) : "f"(f)); return r;
}
__device__ __forceinline__ u64 pk2(float lo, float hi) {
    u64 r; asm("mov.b64 %0, {%1, %2};" : "=l"(r) : "f"(lo), "f"(hi)); return r;
}
__device__ __forceinline__ void upk2(u64 v, float& lo, float& hi) {
    asm("mov.b64 {%0, %1}, %2;" : "=f"(lo), "=f"(hi) : "l"(v));
}
__device__ __forceinline__ u64 fma2(u64 a, u64 b, u64 c) {
    u64 r; asm("fma.rn.f32x2 %0, %1, %2, %3;" : "=l"(r) : "l"(a), "l"(b), "l"(c)); return r;
}
__device__ __forceinline__ u64 mul2(u64 a, u64 b) {
    u64 r; asm("mul.rn.f32x2 %0, %1, %2;" : "=l"(r) : "l"(a), "l"(b)); return r;
}

// 9-term SH dot, SINGLE sequential chain per f32x2 half — exact R1 rounding
// order (verified rel_err 4.8e-8). DO NOT re-associate.
__device__ __forceinline__ u64 sig9p(const u64* C, ulonglong2 q0, ulonglong2 q1,
                                     ulonglong2 q2, ulonglong2 q3, u64 y8) {
    u64 acc = mul2(C[0], q0.x);
    acc = fma2(C[1], q0.y, acc);
    acc = fma2(C[2], q1.x, acc);
    acc = fma2(C[3], q1.y, acc);
    acc = fma2(C[4], q2.x, acc);
    acc = fma2(C[5], q2.y, acc);
    acc = fma2(C[6], q3.x, acc);
    acc = fma2(C[7], q3.y, acc);
    acc = fma2(C[8], y8, acc);
    return acc;
}
__device__ __forceinline__ u64 dot3p(u64 zx, u64 zy, u64 zz, u64 gx, u64 gy, u64 gz) {
    u64 d = mul2(zx, gx);
    d = fma2(zy, gy, d);
    return fma2(zz, gz, d);
}
__device__ __forceinline__ void amax2(u64 s, int g0, float& bv, int& bi) {
    float lo, hi; upk2(s, lo, hi);
    if (lo > bv) { bv = lo; bi = g0; }
    if (hi > bv) { bv = hi; bi = g0 + 1; }
}
__device__ __forceinline__ void amaxm2(u64 s, u64 d, int g0, float& bv, int& bi) {
    float lo, hi, dl, dh; upk2(s, lo, hi); upk2(d, dl, dh);
    if (fabsf(dl) < 0.2f && lo > bv) { bv = lo; bi = g0; }
    if (fabsf(dh) < 0.2f && hi > bv) { bv = hi; bi = g0 + 1; }
}

__device__ __forceinline__ void shY(const float* __restrict__ grid, int g,
                                    float* Y, float* gv) {
    float gx = grid[3 * g + 0], gy = grid[3 * g + 1], gz = grid[3 * g + 2];
    gv[0] = gx; gv[1] = gy; gv[2] = gz;
    float n = sqrtf(gx * gx + gy * gy + gz * gz);
    float inv = 1.0f / fmaxf(n, 1e-12f);
    float x = gx * inv, y = gy * inv, z = gz * inv;
    float x2 = x * x, y2 = y * y, z2 = z * z;
    Y[0] = 2.5033429417967046f * (x * y * (x2 - y2));
    Y[1] = 1.7701307697799304f * (y * z * (3.0f * x2 - y2));
    Y[2] = 0.9461746957575601f * (x * y * (7.0f * z2 - 1.0f));
    Y[3] = 0.6690465435572892f * (y * z * (7.0f * z2 - 3.0f));
    Y[4] = 0.10578554691520431f * (35.0f * z2 * z2 - 30.0f * z2 + 3.0f);
    Y[5] = 0.6690465435572892f * (x * z * (7.0f * z2 - 3.0f));
    Y[6] = 0.47308734787878004f * ((x2 - y2) * (7.0f * z2 - 1.0f));
    Y[7] = 1.7701307697799304f * (x * z * (x2 - y2));
    Y[8] = 0.6258357354491761f * (x2 * x2 - 6.0f * x2 * y2 + y2 * y2);
}

// precompute SH table; also initializes per-row reduction scratch (fused).
__global__ void sh_precompute(const float* __restrict__ grid, int G, int P, int B) {
    int i = blockIdx.x * blockDim.x + threadIdx.x;
    if (i < B) { g_part1[i] = INIT_CAND; g_part2[i] = INIT_CAND; }
    if (i >= P) return;
    int g0 = 2 * i;
    int g1 = min(2 * i + 1, G - 1);
    float Ya[9], Yb[9], ga[3], gb[3];
    shY(grid, g0, Ya, ga);
    shY(grid, g1, Yb, gb);
    T1e t1; T2e t2;
#pragma unroll
    for (int q = 0; q < 9; q++) {
        u64 pr = pk2(Ya[q], Yb[q]);
        t1.v[q] = pr; t2.v[q] = pr;
    }
    t1.v[9] = 0;
    t2.v[9]  = pk2(ga[0], gb[0]);
    t2.v[10] = pk2(ga[1], gb[1]);
    t2.v[11] = pk2(ga[2], gb[2]);
    g_T1[i] = t1;
    g_T2[i] = t2;
}

__device__ __forceinline__ void stage16(const char* gsrc, uint32_t sdst, int bytes, int tid) {
    for (int i = tid * 16; i < bytes; i += BLOCK * 16)
        asm volatile("cp.async.cg.shared.global [%0], [%1], 16;"
                     :: "r"(sdst + (uint32_t)i), "l"(gsrc + i));
}
#define CPA_COMMIT() asm volatile("cp.async.commit_group;" ::: "memory")
#define CPA_WAIT1()  asm volatile("cp.async.wait_group 1;" ::: "memory")

// ---------------------------------------------------------------------------
// Pass 1: blockIdx.x selects 64 rows, blockIdx.y selects g-range slice.
// Partial per-row argmax merged globally via atomicMax on packed u64 keys.
// ---------------------------------------------------------------------------
__global__ __launch_bounds__(BLOCK, 3) void pass1_kernel(
    const float* __restrict__ f4, int B, int P, int Pq)
{
    __shared__ __align__(16) char sbuf[2][CHP * 80];
    __shared__ float s_pv[NW][RPB];
    __shared__ int s_pidx[NW][RPB];

    const int tid = threadIdx.x;
    const int lane = tid & 31;
    const int wid = tid >> 5;
    const int rowbase = blockIdx.x * RPB;
    const int p0 = blockIdx.y * Pq;
    const int np = min(P - p0, Pq);
    const float NEG_INF = __int_as_float(0xff800000);

    const int rA = rowbase + lane;
    const int rB = rA + 32;

    u64 FA[9], FB[9];
#pragma unroll
    for (int i = 0; i < 9; i++) {
        FA[i] = dup2((rA < B) ? f4[rA * 9 + i] : 0.0f);
        FB[i] = dup2((rB < B) ? f4[rB * 9 + i] : 0.0f);
    }

    const int nch = (np + CHP - 1) / CHP;
    uint32_t sb[2];
    sb[0] = (uint32_t)__cvta_generic_to_shared(sbuf[0]);
    sb[1] = (uint32_t)__cvta_generic_to_shared(sbuf[1]);

    float bvA = NEG_INF, bvB = NEG_INF;
    int biA = 0, biB = 0;

    stage16((const char*)(g_T1 + p0), sb[0], min(CHP, np) * 80, tid);
    CPA_COMMIT();
    for (int c = 0; c < nch; c++) {
        int nxt = c + 1;
        if (nxt < nch)
            stage16((const char*)(g_T1 + p0 + nxt * CHP), sb[nxt & 1],
                    min(CHP, np - nxt * CHP) * 80, tid);
        CPA_COMMIT();
        CPA_WAIT1();
        __syncthreads();
        const char* buf = sbuf[c & 1];
        const int cnt = min(CHP, np - c * CHP);
        const int gb = (p0 + c * CHP) * 2;
        for (int k = wid; k < cnt; k += NW) {
            const ulonglong2* e = (const ulonglong2*)(buf + k * 80);
            ulonglong2 q0 = e[0], q1 = e[1], q2 = e[2], q3 = e[3], q4 = e[4];
            u64 aA = sig9p(FA, q0, q1, q2, q3, q4.x);
            u64 aB = sig9p(FB, q0, q1, q2, q3, q4.x);
            int g0 = gb + 2 * k;
            amax2(aA, g0, bvA, biA);
            amax2(aB, g0, bvB, biB);
        }
        __syncthreads();
    }

    s_pv[wid][lane] = bvA;      s_pidx[wid][lane] = biA;
    s_pv[wid][lane + 32] = bvB; s_pidx[wid][lane + 32] = biB;
    __syncthreads();
    if (tid < RPB) {
        int row = rowbase + tid;
        if (row < B) {
            float v = s_pv[0][tid]; int idx = s_pidx[0][tid];
#pragma unroll
            for (int w = 1; w < NW; w++) {
                float ov = s_pv[w][tid]; int oi = s_pidx[w][tid];
                if (ov > v || (ov == v && oi < idx)) { v = ov; idx = oi; }
            }
            atomicMax((unsigned long long*)&g_part1[row], packcand(v, idx));
        }
    }
}

// ---------------------------------------------------------------------------
// Pass 2: masked argmax; z axis read inline from g_part1 (select_z fused).
// ---------------------------------------------------------------------------
__global__ __launch_bounds__(BLOCK, 3) void pass2_kernel(
    const float* __restrict__ f4, const float* __restrict__ grid,
    int B, int P, int Pq)
{
    __shared__ __align__(16) char sbuf[2][CHP * 96];
    __shared__ float s_pv[NW][RPB];
    __shared__ int s_pidx[NW][RPB];

    const int tid = threadIdx.x;
    const int lane = tid & 31;
    const int wid = tid >> 5;
    const int rowbase = blockIdx.x * RPB;
    const int p0 = blockIdx.y * Pq;
    const int np = min(P - p0, Pq);
    const float NEG_INF = __int_as_float(0xff800000);

    const int rA = rowbase + lane;
    const int rB = rA + 32;

    u64 FA[9], FB[9];
#pragma unroll
    for (int i = 0; i < 9; i++) {
        FA[i] = dup2((rA < B) ? f4[rA * 9 + i] : 0.0f);
        FB[i] = dup2((rB < B) ? f4[rB * 9 + i] : 0.0f);
    }
    int izA = (rA < B) ? ~(unsigned)g_part1[rA] : 0;
    int izB = (rB < B) ? ~(unsigned)g_part1[rB] : 0;
    const u64 ZAx = dup2(grid[3 * izA + 0]), ZAy = dup2(grid[3 * izA + 1]), ZAz = dup2(grid[3 * izA + 2]);
    const u64 ZBx = dup2(grid[3 * izB + 0]), ZBy = dup2(grid[3 * izB + 1]), ZBz = dup2(grid[3 * izB + 2]);

    const int nch = (np + CHP - 1) / CHP;
    uint32_t sb[2];
    sb[0] = (uint32_t)__cvta_generic_to_shared(sbuf[0]);
    sb[1] = (uint32_t)__cvta_generic_to_shared(sbuf[1]);

    float bvA = NEG_INF, bvB = NEG_INF;
    int biA = 0, biB = 0;

    stage16((const char*)(g_T2 + p0), sb[0], min(CHP, np) * 96, tid);
    CPA_COMMIT();
    for (int c = 0; c < nch; c++) {
        int nxt = c + 1;
        if (nxt < nch)
            stage16((const char*)(g_T2 + p0 + nxt * CHP), sb[nxt & 1],
                    min(CHP, np - nxt * CHP) * 96, tid);
        CPA_COMMIT();
        CPA_WAIT1();
        __syncthreads();
        const char* buf = sbuf[c & 1];
        const int cnt = min(CHP, np - c * CHP);
        const int gb = (p0 + c * CHP) * 2;
        for (int k = wid; k < cnt; k += NW) {
            const ulonglong2* e = (const ulonglong2*)(buf + k * 96);
            ulonglong2 q0 = e[0], q1 = e[1], q2 = e[2], q3 = e[3], q4 = e[4], q5 = e[5];
            u64 aA = sig9p(FA, q0, q1, q2, q3, q4.x);
            u64 aB = sig9p(FB, q0, q1, q2, q3, q4.x);
            u64 dA = dot3p(ZAx, ZAy, ZAz, q4.y, q5.x, q5.y);
            u64 dB = dot3p(ZBx, ZBy, ZBz, q4.y, q5.x, q5.y);
            int g0 = gb + 2 * k;
            amaxm2(aA, dA, g0, bvA, biA);
            amaxm2(aB, dB, g0, bvB, biB);
        }
        __syncthreads();
    }

    s_pv[wid][lane] = bvA;      s_pidx[wid][lane] = biA;
    s_pv[wid][lane + 32] = bvB; s_pidx[wid][lane + 32] = biB;
    __syncthreads();
    if (tid < RPB) {
        int row = rowbase + tid;
        if (row < B) {
            float v = s_pv[0][tid]; int idx = s_pidx[0][tid];
#pragma unroll
            for (int w = 1; w < NW; w++) {
                float ov = s_pv[w][tid]; int oi = s_pidx[w][tid];
                if (ov > v || (ov == v && oi < idx)) { v = ov; idx = oi; }
            }
            atomicMax((unsigned long long*)&g_part2[row], packcand(v, idx));
        }
    }
}

// ---------------------------------------------------------------------------
// Epilogue: Gram-Schmidt + matrix->quaternion + boundary map.
// ---------------------------------------------------------------------------
__global__ void epilogue_kernel(const float* __restrict__ f0,
                                const float* __restrict__ grid,
                                float* __restrict__ out, int B)
{
    int row = blockIdx.x * blockDim.x + threadIdx.x;
    if (row >= B) return;
    int zi = ~(unsigned)g_part1[row];
    int xi = ~(unsigned)g_part2[row];
    float xr0 = grid[3 * xi + 0], xr1 = grid[3 * xi + 1], xr2 = grid[3 * xi + 2];
    float zr0 = grid[3 * zi + 0], zr1 = grid[3 * zi + 1], zr2 = grid[3 * zi + 2];
    float zn = sqrtf(zr0 * zr0 + zr1 * zr1 + zr2 * zr2);
    float zinv = 1.0f / fmaxf(zn, 1e-12f);
    float z0 = zr0 * zinv, z1 = zr1 * zinv, z2 = zr2 * zinv;
    float pr = xr0 * z0 + xr1 * z1 + xr2 * z2;
    float x0 = xr0 - pr * z0, x1 = xr1 - pr * z1, x2 = xr2 - pr * z2;
    float xn = sqrtf(x0 * x0 + x1 * x1 + x2 * x2);
    float xinv = 1.0f / fmaxf(xn, 1e-12f);
    x0 *= xinv; x1 *= xinv; x2 *= xinv;
    float y0 = z1 * x2 - z2 * x1;
    float y1 = z2 * x0 - z0 * x2;
    float y2 = z0 * x1 - z1 * x0;
    float m00 = x0, m01 = y0, m02 = z0;
    float m10 = x1, m11 = y1, m12 = z1;
    float m20 = x2, m21 = y2, m22 = z2;
    float qa0 = sqrtf(fmaxf(1.0f + m00 + m11 + m22, 0.0f));
    float qa1 = sqrtf(fmaxf(1.0f + m00 - m11 - m22, 0.0f));
    float qa2 = sqrtf(fmaxf(1.0f - m00 + m11 - m22, 0.0f));
    float qa3 = sqrtf(fmaxf(1.0f - m00 - m11 + m22, 0.0f));
    float c0[4] = {qa0 * qa0, m21 - m12, m02 - m20, m10 - m01};
    float c1[4] = {m21 - m12, qa1 * qa1, m10 + m01, m02 + m20};
    float c2[4] = {m02 - m20, m10 + m01, qa2 * qa2, m12 + m21};
    float c3[4] = {m10 - m01, m20 + m02, m21 + m12, qa3 * qa3};
    int best = 0; float bq = qa0;
    if (qa1 > bq) { bq = qa1; best = 1; }
    if (qa2 > bq) { bq = qa2; best = 2; }
    if (qa3 > bq) { bq = qa3; best = 3; }
    const float* cr = (best == 0) ? c0 : (best == 1) ? c1 : (best == 2) ? c2 : c3;
    float dn = 2.0f * fmaxf(bq, 0.1f);
    out[row * 4 + 0] = cr[0] / dn;
    out[row * 4 + 1] = cr[1] / dn;
    out[row * 4 + 2] = cr[2] / dn;
    out[row * 4 + 3] = cr[3] / dn;
    out[4 * B + row] = f0[row] * 57.29577951308232f;
}

extern "C" void kernel_launch(void* const* d_in, const int* in_sizes, int n_in,
                              void* d_out, int out_size) {
    const float* f0 = (const float*)d_in[0];
    const float* f4 = (const float*)d_in[2];
    const float* grid = (const float*)d_in[4];
    int B = in_sizes[0];
    int G = in_sizes[4] / 3;
    if (G > GMAX) G = GMAX;
    if (B > BMAX) B = BMAX;
    int P = (G + 1) / 2;
    int Pq = (P + SPLIT - 1) / SPLIT;

    int pre_n = (P > B) ? P : B;
    sh_precompute<<<(pre_n + 255) / 256, 256>>>(grid, G, P, B);

    dim3 gsplit((B + RPB - 1) / RPB, SPLIT);
    pass1_kernel<<<gsplit, BLOCK>>>(f4, B, P, Pq);
    pass2_kernel<<<gsplit, BLOCK>>>(f4, grid, B, P, Pq);
    epilogue_kernel<<<(B + 255) / 256, 256>>>(f0, grid, (float*)d_out, B);
}